// round 15
// baseline (speedup 1.0000x reference)
#include <cuda_runtime.h>
#include <cstdint>

#define BB 16
#define NN 2000
#define DD 128
#define OO 64
#define NL 3
#define NPAD 2048
#define BN (BB*NN)
#define NCH 125
#define CH 16
#define GT 25
#define NP1 (NN+1)
#define HSS 36

__device__ float g_h[BN*DD];
__device__ float g_Wh[BN*DD];
__device__ float g_e1[2][BN];
__device__ float g_e2[BN];
__device__ float g_e2max[BB];
__device__ int   g_perm[BB*NPAD];
__device__ int   g_k[BN];
__device__ float g_u1[BB*NN];
__device__ float g_u2[BB*NN];
__device__ float g_P2l[BB*NP1*DD];
__device__ float g_P1l[BB*NP1*DD];
__device__ float g_P2ls[BB*NP1];
__device__ float g_P1ls[BB*NP1];
__device__ float g_chF[BB*NCH*DD];
__device__ float g_chB[BB*NCH*DD];
__device__ float g_chF2[BB*NCH*DD];
__device__ float g_chB2[BB*NCH*DD];
__device__ float g_chFs[BB*NCH];
__device__ float g_chBs[BB*NCH];
__device__ float g_chFs2[BB*NCH];
__device__ float g_chBs2[BB*NCH];
__device__ float g_TB[BB*DD];
__device__ float g_TBs[BB];
__device__ int   g_cnt[BB];           // zero-initialized; self-resetting

// ---------- f32x2 packed helpers ----------
__device__ __forceinline__ unsigned long long pk2(float lo, float hi) {
    unsigned long long r;
    asm("mov.b64 %0, {%1, %2};" : "=l"(r)
        : "r"(__float_as_uint(lo)), "r"(__float_as_uint(hi)));
    return r;
}
__device__ __forceinline__ void upk2(unsigned long long v, float& lo, float& hi) {
    unsigned int a, b;
    asm("mov.b64 {%0, %1}, %2;" : "=r"(a), "=r"(b) : "l"(v));
    lo = __uint_as_float(a); hi = __uint_as_float(b);
}
__device__ __forceinline__ unsigned long long fma2(unsigned long long a,
                                                   unsigned long long b,
                                                   unsigned long long c) {
    unsigned long long d;
    asm("fma.rn.f32x2 %0, %1, %2, %3;" : "=l"(d) : "l"(a), "l"(b), "l"(c));
    return d;
}
__device__ __forceinline__ unsigned int xf(float f) {
    unsigned int u = __float_as_uint(f);
    return (u & 0x80000000u) ? ~u : (u | 0x80000000u);
}
__device__ __forceinline__ float ixf(unsigned int u) {
    unsigned int b = (u & 0x80000000u) ? (u & 0x7FFFFFFFu) : ~u;
    return __uint_as_float(b);
}

__device__ __forceinline__ void gemm32(const float* __restrict__ M, const float* hs,
                                       int t, int ldm, unsigned long long* acc) {
#pragma unroll 2
    for (int k = 0; k < DD; k++) {
        float wv = M[k*ldm + t];
        unsigned long long w2 = pk2(wv, wv);
        const float4* hp = (const float4*)(hs + k*HSS);
#pragma unroll
        for (int q = 0; q < 8; q++) {
            float4 h4 = hp[q];
            acc[2*q]   = fma2(pk2(h4.x, h4.y), w2, acc[2*q]);
            acc[2*q+1] = fma2(pk2(h4.z, h4.w), w2, acc[2*q+1]);
        }
    }
}

// ---------- combine: per-node scalars from tables ----------
__device__ __forceinline__ void combine_prelude(int node, const float* __restrict__ e1src,
                                                int* s_ro_ch, int* s_ro_k, int* s_tb,
                                                float* s_a, float* s_be, float* s_inv,
                                                int slot) {
    int b = node / NN;
    int k = g_k[node];
    int c = k >> 4; if (c > NCH - 1) c = NCH - 1;
    float e1v = e1src[node];
    float tt = e1v + g_e2max[b];
    float m = fmaxf(tt, 0.2f * tt);
    float alpha = __expf(tt - m);
    float beta  = __expf(0.2f * tt - m);
    float P2s = g_chFs2[b*NCH + c] + g_P2ls[b*NP1 + k];
    float S1s = g_TBs[b] - (g_chBs2[b*NCH + c] + g_P1ls[b*NP1 + k]);
    float Z = alpha * S1s + beta * P2s;
    s_ro_ch[slot] = (b*NCH + c)*DD;
    s_ro_k[slot]  = (b*NP1 + k)*DD;
    s_tb[slot]    = b*DD;
    s_a[slot] = alpha; s_be[slot] = beta; s_inv[slot] = 1.0f / Z;
}
__device__ __forceinline__ float combine_val(int ro_ch, int ro_k, int tb,
                                             float a, float be, float inv, int d) {
    float P2v = g_chF2[ro_ch + d] + g_P2l[ro_k + d];
    float S1v = g_TB[tb + d] - (g_chB2[ro_ch + d] + g_P1l[ro_k + d]);
    float num = a * S1v + be * P2v;
    return fmaxf(num * inv, 0.f);
}

// ---------------- encoder ----------------
__global__ void enc_kernel(const float* __restrict__ coords, const float* __restrict__ w0,
                           const float* __restrict__ b0, const float* __restrict__ w1,
                           const float* __restrict__ b1) {
    __shared__ float hs[DD*HSS];
    __shared__ float cxy[64];
    int t = threadIdx.x;
    int base = blockIdx.x * 32;
    if (t < 64) cxy[t] = coords[(size_t)base*2 + t];
    __syncthreads();
    float w00 = w0[t], w01 = w0[DD + t], bb = b0[t];
#pragma unroll
    for (int i = 0; i < 32; i++)
        hs[t*HSS + i] = fmaxf(fmaf(cxy[2*i], w00, fmaf(cxy[2*i+1], w01, bb)), 0.f);
    __syncthreads();
    unsigned long long acc[16];
    float bv = b1[t];
    unsigned long long b2 = pk2(bv, bv);
#pragma unroll
    for (int q = 0; q < 16; q++) acc[q] = b2;
    gemm32(w1, hs, t, DD, acc);
#pragma unroll
    for (int q = 0; q < 16; q++) {
        float lo, hi; upk2(acc[q], lo, hi);
        int i = 2*q;
        g_h[(size_t)(base + i)*DD + t] = lo;
        g_h[(size_t)(base + i + 1)*DD + t] = hi;
    }
}

// ---------------- Wh = h @ W + fused e1/e2 (+ optional fused combine) ----------------
template<bool FUSED>
__global__ void whe_kernel(const float* __restrict__ W, const float* __restrict__ a1,
                           const float* __restrict__ a2, int p) {
    __shared__ float hs[DD*HSS];
    __shared__ float red[2][4][32];
    __shared__ int s_ro_ch[32], s_ro_k[32], s_tb[32];
    __shared__ float s_a[32], s_be[32], s_inv[32];
    int t = threadIdx.x;              // 128
    int base = blockIdx.x * 32;
    if (FUSED) {
        if (t < 32)
            combine_prelude(base + t, g_e1[1 - p], s_ro_ch, s_ro_k, s_tb,
                            s_a, s_be, s_inv, t);
        __syncthreads();
#pragma unroll 4
        for (int i = 0; i < 32; i++)
            hs[t*HSS + i] = combine_val(s_ro_ch[i], s_ro_k[i], s_tb[i],
                                        s_a[i], s_be[i], s_inv[i], t);
    } else {
#pragma unroll
        for (int i = 0; i < 32; i++) hs[t*HSS + i] = g_h[(size_t)(base + i)*DD + t];
    }
    __syncthreads();
    unsigned long long acc[16];
#pragma unroll
    for (int q = 0; q < 16; q++) acc[q] = 0ull;
    gemm32(W, hs, t, DD, acc);
    float vals[32];
#pragma unroll
    for (int q = 0; q < 16; q++) upk2(acc[q], vals[2*q], vals[2*q+1]);
#pragma unroll
    for (int i = 0; i < 32; i++) g_Wh[(size_t)(base + i)*DD + t] = vals[i];
    float a1t = a1[t], a2t = a2[t];
    int lane = t & 31, w2i = t >> 5;
#pragma unroll
    for (int i = 0; i < 32; i++) {
        float s1 = vals[i] * a1t, s2 = vals[i] * a2t;
#pragma unroll
        for (int off = 16; off; off >>= 1) {
            s1 += __shfl_xor_sync(0xffffffffu, s1, off);
            s2 += __shfl_xor_sync(0xffffffffu, s2, off);
        }
        if (lane == 0) { red[0][w2i][i] = s1; red[1][w2i][i] = s2; }
    }
    __syncthreads();
    if (t < 64) {
        int which = t >> 5, i = t & 31;
        float s = red[which][0][i] + red[which][1][i] + red[which][2][i] + red[which][3][i];
        if (which == 0) g_e1[p][base + i] = s; else g_e2[base + i] = s;
    }
}

// ---------------- sort: 1024 threads; k<=64 fully in registers ----------------
__global__ void __launch_bounds__(1024) sort_kernel(int p) {
    __shared__ unsigned long long kv[NPAD];
    int b = blockIdx.x, tid = threadIdx.x;      // 1024
    int i0 = 2*tid, i1 = i0 + 1;
    unsigned long long v0, v1;
    v0 = (i0 < NN) ? (((unsigned long long)xf(g_e2[b*NN + i0]) << 32) | (unsigned int)i0)
                   : 0xFFFFFFFFFFFFFFFFull;
    v1 = (i1 < NN) ? (((unsigned long long)xf(g_e2[b*NN + i1]) << 32) | (unsigned int)i1)
                   : 0xFFFFFFFFFFFFFFFFull;
#pragma unroll
    for (int k = 2; k <= 64; k <<= 1) {
        bool up = ((i0 & k) == 0);
        for (int j = k >> 1; j >= 2; j >>= 1) {
            int dlt = j >> 1;
            unsigned long long q0 = __shfl_xor_sync(0xffffffffu, v0, dlt);
            unsigned long long q1 = __shfl_xor_sync(0xffffffffu, v1, dlt);
            bool lower = ((tid & dlt) == 0);
            bool asc = (lower == up);
            if (asc ? (q0 < v0) : (q0 > v0)) v0 = q0;
            if (asc ? (q1 < v1) : (q1 > v1)) v1 = q1;
        }
        if (up ? (v0 > v1) : (v0 < v1)) {
            unsigned long long tv = v0; v0 = v1; v1 = tv;
        }
    }
    kv[i0] = v0; kv[i1] = v1;
    __syncthreads();
    for (int k = 128; k <= NPAD; k <<= 1) {
        for (int j = k >> 1; j >= 64; j >>= 1) {
#pragma unroll
            for (int rep = 0; rep < 2; rep++) {
                int i = tid + rep*1024;
                int ixj = i ^ j;
                if (ixj > i) {
                    bool up = ((i & k) == 0);
                    unsigned long long a = kv[i], c2 = kv[ixj];
                    if (up ? (a > c2) : (a < c2)) { kv[i] = c2; kv[ixj] = a; }
                }
            }
            __syncthreads();
        }
        v0 = kv[i0]; v1 = kv[i1];
        bool up = ((i0 & k) == 0);
        for (int j = 32; j >= 2; j >>= 1) {
            int dlt = j >> 1;
            unsigned long long q0 = __shfl_xor_sync(0xffffffffu, v0, dlt);
            unsigned long long q1 = __shfl_xor_sync(0xffffffffu, v1, dlt);
            bool lower = ((tid & dlt) == 0);
            bool asc = (lower == up);
            if (asc ? (q0 < v0) : (q0 > v0)) v0 = q0;
            if (asc ? (q1 < v1) : (q1 > v1)) v1 = q1;
        }
        if (up ? (v0 > v1) : (v0 < v1)) {
            unsigned long long tv = v0; v0 = v1; v1 = tv;
        }
        kv[i0] = v0; kv[i1] = v1;
        __syncthreads();
    }
    float e2m = ixf((unsigned int)(kv[NN - 1] >> 32));
    if (tid == 0) g_e2max[b] = e2m;
#pragma unroll
    for (int rep = 0; rep < 2; rep++) {
        int i = tid + rep*1024;
        unsigned long long v = kv[i];
        g_perm[b*NPAD + i] = (int)(v & 0xFFFFFFFFu);
        if (i < NN) {
            float ev = ixf((unsigned int)(v >> 32)) - e2m;
            g_u1[b*NN + i] = __expf(ev);
            g_u2[b*NN + i] = __expf(0.2f * ev);
        }
    }
    const float* e1p = g_e1[p];
#pragma unroll
    for (int rep = 0; rep < 2; rep++) {
        int i = tid + rep*1024;
        if (i < NN) {
            unsigned int uv = xf(-e1p[b*NN + i]);
            int lo = 0, hi = NN;
            while (lo < hi) {
                int mid = (lo + hi) >> 1;
                if ((unsigned int)(kv[mid] >> 32) < uv) lo = mid + 1; else hi = mid;
            }
            g_k[b*NN + i] = lo;
        }
    }
}

// ---------------- scanAB + fused scanC (last block per batch) ----------------
__global__ void scanAB_kernel() {
    __shared__ float su1[CH], su2[CH];
    __shared__ int sperm[CH];
    __shared__ int s_last;
    int b = blockIdx.x / NCH, c = blockIdx.x % NCH;
    int d = threadIdx.x;
    int k0 = c * CH;
    if (d < CH) {
        su1[d] = g_u1[b*NN + k0 + d];
        su2[d] = g_u2[b*NN + k0 + d];
        sperm[d] = g_perm[b*NPAD + k0 + d];
    }
    __syncthreads();
    float w[CH];
#pragma unroll
    for (int k = 0; k < CH; k++) w[k] = g_Wh[((size_t)b*NN + sperm[k])*DD + d];
    size_t rowbase = ((size_t)b*NP1 + k0)*DD + d;
    float f = 0.f, bk = 0.f;
#pragma unroll
    for (int k = 0; k < CH; k++) {
        g_P2l[rowbase + (size_t)k*DD] = f;
        g_P1l[rowbase + (size_t)k*DD] = bk;
        f  = fmaf(su2[k], w[k], f);
        bk = fmaf(su1[k], w[k], bk);
    }
    if (c == NCH - 1) {
        g_P2l[rowbase + (size_t)CH*DD] = f;
        g_P1l[rowbase + (size_t)CH*DD] = bk;
    }
    g_chF[(b*NCH + c)*DD + d] = f;
    g_chB[(b*NCH + c)*DD + d] = bk;
    if (d == 0) {
        float s = 0.f;
#pragma unroll
        for (int k = 0; k < CH; k++) { g_P2ls[b*NP1 + k0 + k] = s; s += su2[k]; }
        if (c == NCH - 1) g_P2ls[b*NP1 + NN] = s;
        g_chFs[b*NCH + c] = s;
    }
    if (d == 1) {
        float s = 0.f;
#pragma unroll
        for (int k = 0; k < CH; k++) { g_P1ls[b*NP1 + k0 + k] = s; s += su1[k]; }
        if (c == NCH - 1) g_P1ls[b*NP1 + NN] = s;
        g_chBs[b*NCH + c] = s;
    }
    // ---- last block of batch b performs the chunk-level scans (scanC) ----
    __threadfence();
    __syncthreads();
    if (d == 0) s_last = (atomicAdd(&g_cnt[b], 1) == NCH - 1);
    __syncthreads();
    if (!s_last) return;
    __threadfence();
    {
        // F chain
        float s = 0.f;
        float v[GT];
        for (int tile = 0; tile < 5; tile++) {
            int c0 = tile*GT;
#pragma unroll
            for (int r = 0; r < GT; r++) v[r] = g_chF[(b*NCH + c0 + r)*DD + d];
#pragma unroll
            for (int r = 0; r < GT; r++) { float x = v[r]; v[r] = s; s += x; }
#pragma unroll
            for (int r = 0; r < GT; r++) g_chF2[(b*NCH + c0 + r)*DD + d] = v[r];
        }
        // B chain
        float s2 = 0.f;
        for (int tile = 0; tile < 5; tile++) {
            int c0 = tile*GT;
#pragma unroll
            for (int r = 0; r < GT; r++) v[r] = g_chB[(b*NCH + c0 + r)*DD + d];
#pragma unroll
            for (int r = 0; r < GT; r++) { float x = v[r]; v[r] = s2; s2 += x; }
#pragma unroll
            for (int r = 0; r < GT; r++) g_chB2[(b*NCH + c0 + r)*DD + d] = v[r];
        }
        g_TB[b*DD + d] = s2;
        if (d == 0) {
            float sc = 0.f;
#pragma unroll 5
            for (int cc = 0; cc < NCH; cc++) {
                float x = g_chFs[b*NCH + cc];
                g_chFs2[b*NCH + cc] = sc;
                sc += x;
            }
            g_cnt[b] = 0;           // reset for next layer / replay
        }
        if (d == 1) {
            float sc = 0.f;
#pragma unroll 5
            for (int cc = 0; cc < NCH; cc++) {
                float x = g_chBs[b*NCH + cc];
                g_chBs2[b*NCH + cc] = sc;
                sc += x;
            }
            g_TBs[b] = sc;
        }
    }
}

// ---------------- proj (fused combine) ----------------
__global__ void proj_kernel(const float* __restrict__ pw, const float* __restrict__ pb,
                            float* __restrict__ out, int p) {
    __shared__ float hs[DD*HSS];
    __shared__ int s_ro_ch[32], s_ro_k[32], s_tb[32];
    __shared__ float s_a[32], s_be[32], s_inv[32];
    int t = threadIdx.x;              // 64
    int base = blockIdx.x * 32;
    if (t < 32)
        combine_prelude(base + t, g_e1[p], s_ro_ch, s_ro_k, s_tb, s_a, s_be, s_inv, t);
    __syncthreads();
#pragma unroll 2
    for (int i = 0; i < 32; i++) {
        hs[t*HSS + i]        = combine_val(s_ro_ch[i], s_ro_k[i], s_tb[i],
                                           s_a[i], s_be[i], s_inv[i], t);
        hs[(t + 64)*HSS + i] = combine_val(s_ro_ch[i], s_ro_k[i], s_tb[i],
                                           s_a[i], s_be[i], s_inv[i], t + 64);
    }
    __syncthreads();
    unsigned long long acc[16];
    float bv = pb[t];
    unsigned long long b2 = pk2(bv, bv);
#pragma unroll
    for (int q = 0; q < 16; q++) acc[q] = b2;
    gemm32(pw, hs, t, OO, acc);
#pragma unroll
    for (int q = 0; q < 16; q++) {
        float lo, hi; upk2(acc[q], lo, hi);
        int i = 2*q;
        out[(size_t)(base + i)*OO + t] = lo;
        out[(size_t)(base + i + 1)*OO + t] = hi;
    }
}

extern "C" void kernel_launch(void* const* d_in, const int* in_sizes, int n_in,
                              void* d_out, int out_size) {
    const float* coords = (const float*)d_in[0];
    const float* enc_w0 = (const float*)d_in[1];
    const float* enc_b0 = (const float*)d_in[2];
    const float* enc_w1 = (const float*)d_in[3];
    const float* enc_b1 = (const float*)d_in[4];
    const float* gat_W  = (const float*)d_in[5];
    const float* gat_a1 = (const float*)d_in[6];
    const float* gat_a2 = (const float*)d_in[7];
    const float* proj_w = (const float*)d_in[8];
    const float* proj_b = (const float*)d_in[9];
    float* out = (float*)d_out;

    enc_kernel<<<BN/32, 128>>>(coords, enc_w0, enc_b0, enc_w1, enc_b1);
    for (int l = 0; l < NL; l++) {
        int p = l & 1;
        if (l == 0)
            whe_kernel<false><<<BN/32, 128>>>(gat_W, gat_a1, gat_a2, p);
        else
            whe_kernel<true><<<BN/32, 128>>>(gat_W + (size_t)l*DD*DD,
                                             gat_a1 + l*DD, gat_a2 + l*DD, p);
        sort_kernel<<<BB, 1024>>>(p);
        scanAB_kernel<<<BB*NCH, 128>>>();
    }
    proj_kernel<<<BN/32, 64>>>(proj_w, proj_b, out, (NL - 1) & 1);
}

// round 16
// speedup vs baseline: 1.0945x; 1.0945x over previous
#include <cuda_runtime.h>
#include <cstdint>

#define BB 16
#define NN 2000
#define DD 128
#define OO 64
#define NL 3
#define NPAD 2048
#define BN (BB*NN)
#define NCH 125
#define CH 16
#define GT 25
#define NP1 (NN+1)
#define HSS 36

__device__ float g_h[BN*DD];
__device__ float g_Wh[BN*DD];
__device__ float g_e1[2][BN];
__device__ float g_e2[BN];
__device__ float g_e2max[BB];
__device__ int   g_perm[BB*NPAD];
__device__ int   g_k[BN];
__device__ float g_u1[BB*NN];
__device__ float g_u2[BB*NN];
__device__ float2 g_Pl[BB*NP1*DD];    // .x = u2-weighted local prefix, .y = u1-weighted
__device__ float g_P2ls[BB*NP1];
__device__ float g_P1ls[BB*NP1];
__device__ float g_chF[BB*NCH*DD];
__device__ float g_chB[BB*NCH*DD];
__device__ float g_chF2[BB*NCH*DD];
__device__ float g_chB2[BB*NCH*DD];
__device__ float g_chFs[BB*NCH];
__device__ float g_chBs[BB*NCH];
__device__ float g_chFs2[BB*NCH];
__device__ float g_chBs2[BB*NCH];
__device__ float g_TB[BB*DD];
__device__ float g_TBs[BB];

// ---------- f32x2 packed helpers ----------
__device__ __forceinline__ unsigned long long pk2(float lo, float hi) {
    unsigned long long r;
    asm("mov.b64 %0, {%1, %2};" : "=l"(r)
        : "r"(__float_as_uint(lo)), "r"(__float_as_uint(hi)));
    return r;
}
__device__ __forceinline__ void upk2(unsigned long long v, float& lo, float& hi) {
    unsigned int a, b;
    asm("mov.b64 {%0, %1}, %2;" : "=r"(a), "=r"(b) : "l"(v));
    lo = __uint_as_float(a); hi = __uint_as_float(b);
}
__device__ __forceinline__ unsigned long long fma2(unsigned long long a,
                                                   unsigned long long b,
                                                   unsigned long long c) {
    unsigned long long d;
    asm("fma.rn.f32x2 %0, %1, %2, %3;" : "=l"(d) : "l"(a), "l"(b), "l"(c));
    return d;
}
__device__ __forceinline__ unsigned int xf(float f) {
    unsigned int u = __float_as_uint(f);
    return (u & 0x80000000u) ? ~u : (u | 0x80000000u);
}
__device__ __forceinline__ float ixf(unsigned int u) {
    unsigned int b = (u & 0x80000000u) ? (u & 0x7FFFFFFFu) : ~u;
    return __uint_as_float(b);
}

__device__ __forceinline__ void gemm32(const float* __restrict__ M, const float* hs,
                                       int t, int ldm, unsigned long long* acc) {
#pragma unroll 2
    for (int k = 0; k < DD; k++) {
        float wv = M[k*ldm + t];
        unsigned long long w2 = pk2(wv, wv);
        const float4* hp = (const float4*)(hs + k*HSS);
#pragma unroll
        for (int q = 0; q < 8; q++) {
            float4 h4 = hp[q];
            acc[2*q]   = fma2(pk2(h4.x, h4.y), w2, acc[2*q]);
            acc[2*q+1] = fma2(pk2(h4.z, h4.w), w2, acc[2*q+1]);
        }
    }
}

// ---------- combine: per-node scalars from tables ----------
__device__ __forceinline__ void combine_prelude(int node, const float* __restrict__ e1src,
                                                int* s_ro_ch, int* s_ro_k, int* s_tb,
                                                float* s_a, float* s_be, float* s_inv,
                                                int slot) {
    int b = node / NN;
    int k = g_k[node];
    int c = k >> 4; if (c > NCH - 1) c = NCH - 1;
    float e1v = e1src[node];
    float tt = e1v + g_e2max[b];
    float m = fmaxf(tt, 0.2f * tt);
    float alpha = __expf(tt - m);
    float beta  = __expf(0.2f * tt - m);
    float P2s = g_chFs2[b*NCH + c] + g_P2ls[b*NP1 + k];
    float S1s = g_TBs[b] - (g_chBs2[b*NCH + c] + g_P1ls[b*NP1 + k]);
    float Z = alpha * S1s + beta * P2s;
    s_ro_ch[slot] = (b*NCH + c)*DD;
    s_ro_k[slot]  = (b*NP1 + k)*DD;
    s_tb[slot]    = b*DD;
    s_a[slot] = alpha; s_be[slot] = beta; s_inv[slot] = 1.0f / Z;
}
__device__ __forceinline__ float combine_val(int ro_ch, int ro_k, int tb,
                                             float a, float be, float inv, int d) {
    float2 pl = g_Pl[ro_k + d];
    float P2v = g_chF2[ro_ch + d] + pl.x;
    float S1v = g_TB[tb + d] - (g_chB2[ro_ch + d] + pl.y);
    float num = a * S1v + be * P2v;
    return fmaxf(num * inv, 0.f);
}

// ---------------- encoder ----------------
__global__ void enc_kernel(const float* __restrict__ coords, const float* __restrict__ w0,
                           const float* __restrict__ b0, const float* __restrict__ w1,
                           const float* __restrict__ b1) {
    __shared__ float hs[DD*HSS];
    __shared__ float cxy[64];
    int t = threadIdx.x;
    int base = blockIdx.x * 32;
    if (t < 64) cxy[t] = coords[(size_t)base*2 + t];
    __syncthreads();
    float w00 = w0[t], w01 = w0[DD + t], bb = b0[t];
#pragma unroll
    for (int i = 0; i < 32; i++)
        hs[t*HSS + i] = fmaxf(fmaf(cxy[2*i], w00, fmaf(cxy[2*i+1], w01, bb)), 0.f);
    __syncthreads();
    unsigned long long acc[16];
    float bv = b1[t];
    unsigned long long b2 = pk2(bv, bv);
#pragma unroll
    for (int q = 0; q < 16; q++) acc[q] = b2;
    gemm32(w1, hs, t, DD, acc);
#pragma unroll
    for (int q = 0; q < 16; q++) {
        float lo, hi; upk2(acc[q], lo, hi);
        int i = 2*q;
        g_h[(size_t)(base + i)*DD + t] = lo;
        g_h[(size_t)(base + i + 1)*DD + t] = hi;
    }
}

// ---------------- Wh = h @ W + fused e1/e2 (+ optional fused combine) ----------------
template<bool FUSED>
__global__ void whe_kernel(const float* __restrict__ W, const float* __restrict__ a1,
                           const float* __restrict__ a2, int p) {
    __shared__ float hs[DD*HSS];
    __shared__ float red[2][4][32];
    __shared__ int s_ro_ch[32], s_ro_k[32], s_tb[32];
    __shared__ float s_a[32], s_be[32], s_inv[32];
    int t = threadIdx.x;              // 128
    int base = blockIdx.x * 32;
    if (FUSED) {
        if (t < 32)
            combine_prelude(base + t, g_e1[1 - p], s_ro_ch, s_ro_k, s_tb,
                            s_a, s_be, s_inv, t);
        __syncthreads();
#pragma unroll 4
        for (int i = 0; i < 32; i++)
            hs[t*HSS + i] = combine_val(s_ro_ch[i], s_ro_k[i], s_tb[i],
                                        s_a[i], s_be[i], s_inv[i], t);
    } else {
#pragma unroll
        for (int i = 0; i < 32; i++) hs[t*HSS + i] = g_h[(size_t)(base + i)*DD + t];
    }
    __syncthreads();
    unsigned long long acc[16];
#pragma unroll
    for (int q = 0; q < 16; q++) acc[q] = 0ull;
    gemm32(W, hs, t, DD, acc);
    float vals[32];
#pragma unroll
    for (int q = 0; q < 16; q++) upk2(acc[q], vals[2*q], vals[2*q+1]);
#pragma unroll
    for (int i = 0; i < 32; i++) g_Wh[(size_t)(base + i)*DD + t] = vals[i];
    float a1t = a1[t], a2t = a2[t];
    int lane = t & 31, w2i = t >> 5;
#pragma unroll
    for (int i = 0; i < 32; i++) {
        float s1 = vals[i] * a1t, s2 = vals[i] * a2t;
#pragma unroll
        for (int off = 16; off; off >>= 1) {
            s1 += __shfl_xor_sync(0xffffffffu, s1, off);
            s2 += __shfl_xor_sync(0xffffffffu, s2, off);
        }
        if (lane == 0) { red[0][w2i][i] = s1; red[1][w2i][i] = s2; }
    }
    __syncthreads();
    if (t < 64) {
        int which = t >> 5, i = t & 31;
        float s = red[which][0][i] + red[which][1][i] + red[which][2][i] + red[which][3][i];
        if (which == 0) g_e1[p][base + i] = s; else g_e2[base + i] = s;
    }
}

// ---------------- sort: 1024 threads; k<=64 fully in registers ----------------
__global__ void __launch_bounds__(1024) sort_kernel(int p) {
    __shared__ unsigned long long kv[NPAD];
    int b = blockIdx.x, tid = threadIdx.x;      // 1024
    int i0 = 2*tid, i1 = i0 + 1;
    unsigned long long v0, v1;
    v0 = (i0 < NN) ? (((unsigned long long)xf(g_e2[b*NN + i0]) << 32) | (unsigned int)i0)
                   : 0xFFFFFFFFFFFFFFFFull;
    v1 = (i1 < NN) ? (((unsigned long long)xf(g_e2[b*NN + i1]) << 32) | (unsigned int)i1)
                   : 0xFFFFFFFFFFFFFFFFull;
#pragma unroll
    for (int k = 2; k <= 64; k <<= 1) {
        bool up = ((i0 & k) == 0);
        for (int j = k >> 1; j >= 2; j >>= 1) {
            int dlt = j >> 1;
            unsigned long long q0 = __shfl_xor_sync(0xffffffffu, v0, dlt);
            unsigned long long q1 = __shfl_xor_sync(0xffffffffu, v1, dlt);
            bool lower = ((tid & dlt) == 0);
            bool asc = (lower == up);
            if (asc ? (q0 < v0) : (q0 > v0)) v0 = q0;
            if (asc ? (q1 < v1) : (q1 > v1)) v1 = q1;
        }
        if (up ? (v0 > v1) : (v0 < v1)) {
            unsigned long long tv = v0; v0 = v1; v1 = tv;
        }
    }
    kv[i0] = v0; kv[i1] = v1;
    __syncthreads();
    for (int k = 128; k <= NPAD; k <<= 1) {
        for (int j = k >> 1; j >= 64; j >>= 1) {
#pragma unroll
            for (int rep = 0; rep < 2; rep++) {
                int i = tid + rep*1024;
                int ixj = i ^ j;
                if (ixj > i) {
                    bool up = ((i & k) == 0);
                    unsigned long long a = kv[i], c2 = kv[ixj];
                    if (up ? (a > c2) : (a < c2)) { kv[i] = c2; kv[ixj] = a; }
                }
            }
            __syncthreads();
        }
        v0 = kv[i0]; v1 = kv[i1];
        bool up = ((i0 & k) == 0);
        for (int j = 32; j >= 2; j >>= 1) {
            int dlt = j >> 1;
            unsigned long long q0 = __shfl_xor_sync(0xffffffffu, v0, dlt);
            unsigned long long q1 = __shfl_xor_sync(0xffffffffu, v1, dlt);
            bool lower = ((tid & dlt) == 0);
            bool asc = (lower == up);
            if (asc ? (q0 < v0) : (q0 > v0)) v0 = q0;
            if (asc ? (q1 < v1) : (q1 > v1)) v1 = q1;
        }
        if (up ? (v0 > v1) : (v0 < v1)) {
            unsigned long long tv = v0; v0 = v1; v1 = tv;
        }
        kv[i0] = v0; kv[i1] = v1;
        __syncthreads();
    }
    float e2m = ixf((unsigned int)(kv[NN - 1] >> 32));
    if (tid == 0) g_e2max[b] = e2m;
#pragma unroll
    for (int rep = 0; rep < 2; rep++) {
        int i = tid + rep*1024;
        unsigned long long v = kv[i];
        g_perm[b*NPAD + i] = (int)(v & 0xFFFFFFFFu);
        if (i < NN) {
            float ev = ixf((unsigned int)(v >> 32)) - e2m;
            g_u1[b*NN + i] = __expf(ev);
            g_u2[b*NN + i] = __expf(0.2f * ev);
        }
    }
    const float* e1p = g_e1[p];
#pragma unroll
    for (int rep = 0; rep < 2; rep++) {
        int i = tid + rep*1024;
        if (i < NN) {
            unsigned int uv = xf(-e1p[b*NN + i]);
            int lo = 0, hi = NN;
            while (lo < hi) {
                int mid = (lo + hi) >> 1;
                if ((unsigned int)(kv[mid] >> 32) < uv) lo = mid + 1; else hi = mid;
            }
            g_k[b*NN + i] = lo;
        }
    }
}

// ---------------- scanAB: gather once; emit interleaved local prefix table ----------------
__global__ void scanAB_kernel() {
    __shared__ float su1[CH], su2[CH];
    __shared__ int sperm[CH];
    int b = blockIdx.x / NCH, c = blockIdx.x % NCH;
    int d = threadIdx.x;
    int k0 = c * CH;
    if (d < CH) {
        su1[d] = g_u1[b*NN + k0 + d];
        su2[d] = g_u2[b*NN + k0 + d];
        sperm[d] = g_perm[b*NPAD + k0 + d];
    }
    __syncthreads();
    float w[CH];
#pragma unroll
    for (int k = 0; k < CH; k++) w[k] = g_Wh[((size_t)b*NN + sperm[k])*DD + d];
    size_t rowbase = ((size_t)b*NP1 + k0)*DD + d;
    float f = 0.f, bk = 0.f;
#pragma unroll
    for (int k = 0; k < CH; k++) {
        g_Pl[rowbase + (size_t)k*DD] = make_float2(f, bk);
        f  = fmaf(su2[k], w[k], f);
        bk = fmaf(su1[k], w[k], bk);
    }
    if (c == NCH - 1) g_Pl[rowbase + (size_t)CH*DD] = make_float2(f, bk);
    g_chF[(b*NCH + c)*DD + d] = f;
    g_chB[(b*NCH + c)*DD + d] = bk;
    if (d == 0) {
        float s = 0.f;
#pragma unroll
        for (int k = 0; k < CH; k++) { g_P2ls[b*NP1 + k0 + k] = s; s += su2[k]; }
        if (c == NCH - 1) g_P2ls[b*NP1 + NN] = s;
        g_chFs[b*NCH + c] = s;
    }
    if (d == 1) {
        float s = 0.f;
#pragma unroll
        for (int k = 0; k < CH; k++) { g_P1ls[b*NP1 + k0 + k] = s; s += su1[k]; }
        if (c == NCH - 1) g_P1ls[b*NP1 + NN] = s;
        g_chBs[b*NCH + c] = s;
    }
}

// ---------------- scanC: F and B chains in separate blocks (grid = 2*BB) ----------------
__global__ void scanC_kernel() {
    int b = blockIdx.x >> 1;
    bool isF = (blockIdx.x & 1) == 0;
    int d = threadIdx.x;
    const float* src = isF ? g_chF : g_chB;
    float* dst = isF ? g_chF2 : g_chB2;
    float s = 0.f;
    float v[GT];
    for (int tile = 0; tile < 5; tile++) {
        int c0 = tile*GT;
#pragma unroll
        for (int r = 0; r < GT; r++) v[r] = src[(b*NCH + c0 + r)*DD + d];
#pragma unroll
        for (int r = 0; r < GT; r++) { float x = v[r]; v[r] = s; s += x; }
#pragma unroll
        for (int r = 0; r < GT; r++) dst[(b*NCH + c0 + r)*DD + d] = v[r];
    }
    if (!isF) g_TB[b*DD + d] = s;
    if (d == 0) {
        const float* ssrc = isF ? g_chFs : g_chBs;
        float* sdst = isF ? g_chFs2 : g_chBs2;
        float sc = 0.f;
#pragma unroll 5
        for (int c = 0; c < NCH; c++) {
            float x = ssrc[b*NCH + c];
            sdst[b*NCH + c] = sc;
            sc += x;
        }
        if (!isF) g_TBs[b] = sc;
    }
}

// ---------------- proj (fused combine) ----------------
__global__ void proj_kernel(const float* __restrict__ pw, const float* __restrict__ pb,
                            float* __restrict__ out, int p) {
    __shared__ float hs[DD*HSS];
    __shared__ int s_ro_ch[32], s_ro_k[32], s_tb[32];
    __shared__ float s_a[32], s_be[32], s_inv[32];
    int t = threadIdx.x;              // 64
    int base = blockIdx.x * 32;
    if (t < 32)
        combine_prelude(base + t, g_e1[p], s_ro_ch, s_ro_k, s_tb, s_a, s_be, s_inv, t);
    __syncthreads();
#pragma unroll 2
    for (int i = 0; i < 32; i++) {
        hs[t*HSS + i]        = combine_val(s_ro_ch[i], s_ro_k[i], s_tb[i],
                                           s_a[i], s_be[i], s_inv[i], t);
        hs[(t + 64)*HSS + i] = combine_val(s_ro_ch[i], s_ro_k[i], s_tb[i],
                                           s_a[i], s_be[i], s_inv[i], t + 64);
    }
    __syncthreads();
    unsigned long long acc[16];
    float bv = pb[t];
    unsigned long long b2 = pk2(bv, bv);
#pragma unroll
    for (int q = 0; q < 16; q++) acc[q] = b2;
    gemm32(pw, hs, t, OO, acc);
#pragma unroll
    for (int q = 0; q < 16; q++) {
        float lo, hi; upk2(acc[q], lo, hi);
        int i = 2*q;
        out[(size_t)(base + i)*OO + t] = lo;
        out[(size_t)(base + i + 1)*OO + t] = hi;
    }
}

extern "C" void kernel_launch(void* const* d_in, const int* in_sizes, int n_in,
                              void* d_out, int out_size) {
    const float* coords = (const float*)d_in[0];
    const float* enc_w0 = (const float*)d_in[1];
    const float* enc_b0 = (const float*)d_in[2];
    const float* enc_w1 = (const float*)d_in[3];
    const float* enc_b1 = (const float*)d_in[4];
    const float* gat_W  = (const float*)d_in[5];
    const float* gat_a1 = (const float*)d_in[6];
    const float* gat_a2 = (const float*)d_in[7];
    const float* proj_w = (const float*)d_in[8];
    const float* proj_b = (const float*)d_in[9];
    float* out = (float*)d_out;

    enc_kernel<<<BN/32, 128>>>(coords, enc_w0, enc_b0, enc_w1, enc_b1);
    for (int l = 0; l < NL; l++) {
        int p = l & 1;
        if (l == 0)
            whe_kernel<false><<<BN/32, 128>>>(gat_W, gat_a1, gat_a2, p);
        else
            whe_kernel<true><<<BN/32, 128>>>(gat_W + (size_t)l*DD*DD,
                                             gat_a1 + l*DD, gat_a2 + l*DD, p);
        sort_kernel<<<BB, 1024>>>(p);
        scanAB_kernel<<<BB*NCH, 128>>>();
        scanC_kernel<<<2*BB, 128>>>();
    }
    proj_kernel<<<BN/32, 64>>>(proj_w, proj_b, out, (NL - 1) & 1);
}

// round 17
// speedup vs baseline: 1.1269x; 1.0296x over previous
#include <cuda_runtime.h>
#include <cstdint>

#define BB 16
#define NN 2000
#define DD 128
#define OO 64
#define NL 3
#define NPAD 2048
#define BN (BB*NN)
#define NCH 125
#define CH 16
#define GT 25
#define NP1 (NN+1)
#define HSS 36

__device__ float g_h[BN*DD];
__device__ float g_Wh[BN*DD];
__device__ float g_e1[2][BN];
__device__ float g_e2[BN];
__device__ float g_e2max[BB];
__device__ int   g_perm[BB*NPAD];
__device__ int   g_k[BN];
__device__ float g_u1[BB*NN];
__device__ float g_u2[BB*NN];
__device__ float2 g_Pl[BB*NP1*DD];    // .x = u2-weighted local prefix, .y = u1-weighted
__device__ float g_P2ls[BB*NP1];
__device__ float g_P1ls[BB*NP1];
__device__ float g_chF[BB*NCH*DD];
__device__ float g_chB[BB*NCH*DD];
__device__ float g_chF2[BB*NCH*DD];
__device__ float g_chB2[BB*NCH*DD];
__device__ float g_chFs[BB*NCH];
__device__ float g_chBs[BB*NCH];
__device__ float g_chFs2[BB*NCH];
__device__ float g_chBs2[BB*NCH];
__device__ float g_TB[BB*DD];
__device__ float g_TBs[BB];

// ---------- f32x2 packed helpers ----------
__device__ __forceinline__ unsigned long long pk2(float lo, float hi) {
    unsigned long long r;
    asm("mov.b64 %0, {%1, %2};" : "=l"(r)
        : "r"(__float_as_uint(lo)), "r"(__float_as_uint(hi)));
    return r;
}
__device__ __forceinline__ void upk2(unsigned long long v, float& lo, float& hi) {
    unsigned int a, b;
    asm("mov.b64 {%0, %1}, %2;" : "=r"(a), "=r"(b) : "l"(v));
    lo = __uint_as_float(a); hi = __uint_as_float(b);
}
__device__ __forceinline__ unsigned long long fma2(unsigned long long a,
                                                   unsigned long long b,
                                                   unsigned long long c) {
    unsigned long long d;
    asm("fma.rn.f32x2 %0, %1, %2, %3;" : "=l"(d) : "l"(a), "l"(b), "l"(c));
    return d;
}
__device__ __forceinline__ unsigned int xf(float f) {
    unsigned int u = __float_as_uint(f);
    return (u & 0x80000000u) ? ~u : (u | 0x80000000u);
}
__device__ __forceinline__ float ixf(unsigned int u) {
    unsigned int b = (u & 0x80000000u) ? (u & 0x7FFFFFFFu) : ~u;
    return __uint_as_float(b);
}

__device__ __forceinline__ void gemm32(const float* __restrict__ M, const float* hs,
                                       int t, int ldm, unsigned long long* acc) {
#pragma unroll 2
    for (int k = 0; k < DD; k++) {
        float wv = M[k*ldm + t];
        unsigned long long w2 = pk2(wv, wv);
        const float4* hp = (const float4*)(hs + k*HSS);
#pragma unroll
        for (int q = 0; q < 8; q++) {
            float4 h4 = hp[q];
            acc[2*q]   = fma2(pk2(h4.x, h4.y), w2, acc[2*q]);
            acc[2*q+1] = fma2(pk2(h4.z, h4.w), w2, acc[2*q+1]);
        }
    }
}

// ---------- combine: per-node scalars from tables ----------
__device__ __forceinline__ void combine_prelude(int node, const float* __restrict__ e1src,
                                                int* s_ro_ch, int* s_ro_k, int* s_tb,
                                                float* s_a, float* s_be, float* s_inv,
                                                int slot) {
    int b = node / NN;
    int k = g_k[node];
    int c = k >> 4; if (c > NCH - 1) c = NCH - 1;
    float e1v = e1src[node];
    float tt = e1v + g_e2max[b];
    float m = fmaxf(tt, 0.2f * tt);
    float alpha = __expf(tt - m);
    float beta  = __expf(0.2f * tt - m);
    float P2s = g_chFs2[b*NCH + c] + g_P2ls[b*NP1 + k];
    float S1s = g_TBs[b] - (g_chBs2[b*NCH + c] + g_P1ls[b*NP1 + k]);
    float Z = alpha * S1s + beta * P2s;
    s_ro_ch[slot] = (b*NCH + c)*DD;
    s_ro_k[slot]  = (b*NP1 + k)*DD;
    s_tb[slot]    = b*DD;
    s_a[slot] = alpha; s_be[slot] = beta; s_inv[slot] = 1.0f / Z;
}
__device__ __forceinline__ float combine_val(int ro_ch, int ro_k, int tb,
                                             float a, float be, float inv, int d) {
    float2 pl = g_Pl[ro_k + d];
    float P2v = g_chF2[ro_ch + d] + pl.x;
    float S1v = g_TB[tb + d] - (g_chB2[ro_ch + d] + pl.y);
    float num = a * S1v + be * P2v;
    return fmaxf(num * inv, 0.f);
}

// ---------------- encoder ----------------
__global__ void enc_kernel(const float* __restrict__ coords, const float* __restrict__ w0,
                           const float* __restrict__ b0, const float* __restrict__ w1,
                           const float* __restrict__ b1) {
    __shared__ float hs[DD*HSS];
    __shared__ float cxy[64];
    int t = threadIdx.x;
    int base = blockIdx.x * 32;
    if (t < 64) cxy[t] = coords[(size_t)base*2 + t];
    __syncthreads();
    float w00 = w0[t], w01 = w0[DD + t], bb = b0[t];
#pragma unroll
    for (int i = 0; i < 32; i++)
        hs[t*HSS + i] = fmaxf(fmaf(cxy[2*i], w00, fmaf(cxy[2*i+1], w01, bb)), 0.f);
    __syncthreads();
    unsigned long long acc[16];
    float bv = b1[t];
    unsigned long long b2 = pk2(bv, bv);
#pragma unroll
    for (int q = 0; q < 16; q++) acc[q] = b2;
    gemm32(w1, hs, t, DD, acc);
#pragma unroll
    for (int q = 0; q < 16; q++) {
        float lo, hi; upk2(acc[q], lo, hi);
        int i = 2*q;
        g_h[(size_t)(base + i)*DD + t] = lo;
        g_h[(size_t)(base + i + 1)*DD + t] = hi;
    }
}

// ---------------- Wh = h @ W + fused e1/e2 (+ optional fused combine) ----------------
template<bool FUSED>
__global__ void whe_kernel(const float* __restrict__ W, const float* __restrict__ a1,
                           const float* __restrict__ a2, int p) {
    __shared__ float hs[DD*HSS];
    __shared__ float red[2][4][32];
    __shared__ int s_ro_ch[32], s_ro_k[32], s_tb[32];
    __shared__ float s_a[32], s_be[32], s_inv[32];
    int t = threadIdx.x;              // 128
    int base = blockIdx.x * 32;
    if (FUSED) {
        if (t < 32)
            combine_prelude(base + t, g_e1[1 - p], s_ro_ch, s_ro_k, s_tb,
                            s_a, s_be, s_inv, t);
        __syncthreads();
#pragma unroll 4
        for (int i = 0; i < 32; i++)
            hs[t*HSS + i] = combine_val(s_ro_ch[i], s_ro_k[i], s_tb[i],
                                        s_a[i], s_be[i], s_inv[i], t);
    } else {
#pragma unroll
        for (int i = 0; i < 32; i++) hs[t*HSS + i] = g_h[(size_t)(base + i)*DD + t];
    }
    __syncthreads();
    unsigned long long acc[16];
#pragma unroll
    for (int q = 0; q < 16; q++) acc[q] = 0ull;
    gemm32(W, hs, t, DD, acc);
    float vals[32];
#pragma unroll
    for (int q = 0; q < 16; q++) upk2(acc[q], vals[2*q], vals[2*q+1]);
#pragma unroll
    for (int i = 0; i < 32; i++) g_Wh[(size_t)(base + i)*DD + t] = vals[i];
    float a1t = a1[t], a2t = a2[t];
    int lane = t & 31, w2i = t >> 5;
#pragma unroll
    for (int i = 0; i < 32; i++) {
        float s1 = vals[i] * a1t, s2 = vals[i] * a2t;
#pragma unroll
        for (int off = 16; off; off >>= 1) {
            s1 += __shfl_xor_sync(0xffffffffu, s1, off);
            s2 += __shfl_xor_sync(0xffffffffu, s2, off);
        }
        if (lane == 0) { red[0][w2i][i] = s1; red[1][w2i][i] = s2; }
    }
    __syncthreads();
    if (t < 64) {
        int which = t >> 5, i = t & 31;
        float s = red[which][0][i] + red[which][1][i] + red[which][2][i] + red[which][3][i];
        if (which == 0) g_e1[p][base + i] = s; else g_e2[base + i] = s;
    }
}

// ---------------- sort: warp-sorted 64-chunks + 5 merge-path rounds ----------------
__global__ void __launch_bounds__(1024) sort_kernel(int p) {
    __shared__ unsigned long long A[NPAD];
    __shared__ unsigned long long Bm[NPAD];
    int b = blockIdx.x, tid = threadIdx.x;      // 1024
    int i0 = 2*tid, i1 = i0 + 1;
    unsigned long long v0, v1;
    v0 = (i0 < NN) ? (((unsigned long long)xf(g_e2[b*NN + i0]) << 32) | (unsigned int)i0)
                   : ((0xFFFFFFFFull << 32) | (unsigned int)i0);
    v1 = (i1 < NN) ? (((unsigned long long)xf(g_e2[b*NN + i1]) << 32) | (unsigned int)i1)
                   : ((0xFFFFFFFFull << 32) | (unsigned int)i1);
    // in-register bitonic sort of each warp's 64-element chunk (ascending)
#pragma unroll
    for (int k = 2; k <= 64; k <<= 1) {
        bool up = (k == 64) ? true : ((i0 & k) == 0);
        for (int j = k >> 1; j >= 2; j >>= 1) {
            int dlt = j >> 1;
            unsigned long long q0 = __shfl_xor_sync(0xffffffffu, v0, dlt);
            unsigned long long q1 = __shfl_xor_sync(0xffffffffu, v1, dlt);
            bool lower = ((tid & dlt) == 0);
            bool asc = (lower == up);
            if (asc ? (q0 < v0) : (q0 > v0)) v0 = q0;
            if (asc ? (q1 < v1) : (q1 > v1)) v1 = q1;
        }
        if (up ? (v0 > v1) : (v0 < v1)) {
            unsigned long long tv = v0; v0 = v1; v1 = tv;
        }
    }
    A[i0] = v0; A[i1] = v1;
    // merge rounds: L = 64, 128, 256, 512, 1024 (keys unique -> exact placement)
    unsigned long long* src = A;
    unsigned long long* dst = Bm;
    for (int L = 64; L <= 1024; L <<= 1) {
        __syncthreads();
#pragma unroll
        for (int rep = 0; rep < 2; rep++) {
            int i = tid + rep*1024;
            unsigned long long key = src[i];
            int pairBase = i & ~(2*L - 1);
            int off = i - pairBase;
            bool left = off < L;
            int sibStart = pairBase + (left ? L : 0);
            int myPos = left ? off : off - L;
            int lo = 0;
            for (int h = L >> 1; h >= 1; h >>= 1)
                if (src[sibStart + lo + h - 1] < key) lo += h;
            lo += (src[sibStart + lo] < key);
            dst[pairBase + myPos + lo] = key;
        }
        unsigned long long* tmp = src; src = dst; dst = tmp;
    }
    __syncthreads();
    // src now holds the fully sorted array
    float e2m = ixf((unsigned int)(src[NN - 1] >> 32));
    if (tid == 0) g_e2max[b] = e2m;
#pragma unroll
    for (int rep = 0; rep < 2; rep++) {
        int i = tid + rep*1024;
        unsigned long long v = src[i];
        g_perm[b*NPAD + i] = (int)(v & 0xFFFFFFFFu);
        if (i < NN) {
            float ev = ixf((unsigned int)(v >> 32)) - e2m;
            g_u1[b*NN + i] = __expf(ev);
            g_u2[b*NN + i] = __expf(0.2f * ev);
        }
    }
    const float* e1p = g_e1[p];
#pragma unroll
    for (int rep = 0; rep < 2; rep++) {
        int i = tid + rep*1024;
        if (i < NN) {
            unsigned int uv = xf(-e1p[b*NN + i]);
            int lo = 0, hi = NN;
            while (lo < hi) {
                int mid = (lo + hi) >> 1;
                if ((unsigned int)(src[mid] >> 32) < uv) lo = mid + 1; else hi = mid;
            }
            g_k[b*NN + i] = lo;
        }
    }
}

// ---------------- scanAB: gather once; emit interleaved local prefix table ----------------
__global__ void scanAB_kernel() {
    __shared__ float su1[CH], su2[CH];
    __shared__ int sperm[CH];
    int b = blockIdx.x / NCH, c = blockIdx.x % NCH;
    int d = threadIdx.x;
    int k0 = c * CH;
    if (d < CH) {
        su1[d] = g_u1[b*NN + k0 + d];
        su2[d] = g_u2[b*NN + k0 + d];
        sperm[d] = g_perm[b*NPAD + k0 + d];
    }
    __syncthreads();
    float w[CH];
#pragma unroll
    for (int k = 0; k < CH; k++) w[k] = g_Wh[((size_t)b*NN + sperm[k])*DD + d];
    size_t rowbase = ((size_t)b*NP1 + k0)*DD + d;
    float f = 0.f, bk = 0.f;
#pragma unroll
    for (int k = 0; k < CH; k++) {
        g_Pl[rowbase + (size_t)k*DD] = make_float2(f, bk);
        f  = fmaf(su2[k], w[k], f);
        bk = fmaf(su1[k], w[k], bk);
    }
    if (c == NCH - 1) g_Pl[rowbase + (size_t)CH*DD] = make_float2(f, bk);
    g_chF[(b*NCH + c)*DD + d] = f;
    g_chB[(b*NCH + c)*DD + d] = bk;
    if (d == 0) {
        float s = 0.f;
#pragma unroll
        for (int k = 0; k < CH; k++) { g_P2ls[b*NP1 + k0 + k] = s; s += su2[k]; }
        if (c == NCH - 1) g_P2ls[b*NP1 + NN] = s;
        g_chFs[b*NCH + c] = s;
    }
    if (d == 1) {
        float s = 0.f;
#pragma unroll
        for (int k = 0; k < CH; k++) { g_P1ls[b*NP1 + k0 + k] = s; s += su1[k]; }
        if (c == NCH - 1) g_P1ls[b*NP1 + NN] = s;
        g_chBs[b*NCH + c] = s;
    }
}

// ---------------- scanC: F and B chains in separate blocks (grid = 2*BB) ----------------
__global__ void scanC_kernel() {
    int b = blockIdx.x >> 1;
    bool isF = (blockIdx.x & 1) == 0;
    int d = threadIdx.x;
    const float* src = isF ? g_chF : g_chB;
    float* dst = isF ? g_chF2 : g_chB2;
    float s = 0.f;
    float v[GT];
    for (int tile = 0; tile < 5; tile++) {
        int c0 = tile*GT;
#pragma unroll
        for (int r = 0; r < GT; r++) v[r] = src[(b*NCH + c0 + r)*DD + d];
#pragma unroll
        for (int r = 0; r < GT; r++) { float x = v[r]; v[r] = s; s += x; }
#pragma unroll
        for (int r = 0; r < GT; r++) dst[(b*NCH + c0 + r)*DD + d] = v[r];
    }
    if (!isF) g_TB[b*DD + d] = s;
    if (d == 0) {
        const float* ssrc = isF ? g_chFs : g_chBs;
        float* sdst = isF ? g_chFs2 : g_chBs2;
        float sc = 0.f;
#pragma unroll 5
        for (int c = 0; c < NCH; c++) {
            float x = ssrc[b*NCH + c];
            sdst[b*NCH + c] = sc;
            sc += x;
        }
        if (!isF) g_TBs[b] = sc;
    }
}

// ---------------- proj (fused combine) ----------------
__global__ void proj_kernel(const float* __restrict__ pw, const float* __restrict__ pb,
                            float* __restrict__ out, int p) {
    __shared__ float hs[DD*HSS];
    __shared__ int s_ro_ch[32], s_ro_k[32], s_tb[32];
    __shared__ float s_a[32], s_be[32], s_inv[32];
    int t = threadIdx.x;              // 64
    int base = blockIdx.x * 32;
    if (t < 32)
        combine_prelude(base + t, g_e1[p], s_ro_ch, s_ro_k, s_tb, s_a, s_be, s_inv, t);
    __syncthreads();
#pragma unroll 2
    for (int i = 0; i < 32; i++) {
        hs[t*HSS + i]        = combine_val(s_ro_ch[i], s_ro_k[i], s_tb[i],
                                           s_a[i], s_be[i], s_inv[i], t);
        hs[(t + 64)*HSS + i] = combine_val(s_ro_ch[i], s_ro_k[i], s_tb[i],
                                           s_a[i], s_be[i], s_inv[i], t + 64);
    }
    __syncthreads();
    unsigned long long acc[16];
    float bv = pb[t];
    unsigned long long b2 = pk2(bv, bv);
#pragma unroll
    for (int q = 0; q < 16; q++) acc[q] = b2;
    gemm32(pw, hs, t, OO, acc);
#pragma unroll
    for (int q = 0; q < 16; q++) {
        float lo, hi; upk2(acc[q], lo, hi);
        int i = 2*q;
        out[(size_t)(base + i)*OO + t] = lo;
        out[(size_t)(base + i + 1)*OO + t] = hi;
    }
}

extern "C" void kernel_launch(void* const* d_in, const int* in_sizes, int n_in,
                              void* d_out, int out_size) {
    const float* coords = (const float*)d_in[0];
    const float* enc_w0 = (const float*)d_in[1];
    const float* enc_b0 = (const float*)d_in[2];
    const float* enc_w1 = (const float*)d_in[3];
    const float* enc_b1 = (const float*)d_in[4];
    const float* gat_W  = (const float*)d_in[5];
    const float* gat_a1 = (const float*)d_in[6];
    const float* gat_a2 = (const float*)d_in[7];
    const float* proj_w = (const float*)d_in[8];
    const float* proj_b = (const float*)d_in[9];
    float* out = (float*)d_out;

    enc_kernel<<<BN/32, 128>>>(coords, enc_w0, enc_b0, enc_w1, enc_b1);
    for (int l = 0; l < NL; l++) {
        int p = l & 1;
        if (l == 0)
            whe_kernel<false><<<BN/32, 128>>>(gat_W, gat_a1, gat_a2, p);
        else
            whe_kernel<true><<<BN/32, 128>>>(gat_W + (size_t)l*DD*DD,
                                             gat_a1 + l*DD, gat_a2 + l*DD, p);
        sort_kernel<<<BB, 1024>>>(p);
        scanAB_kernel<<<BB*NCH, 128>>>();
        scanC_kernel<<<2*BB, 128>>>();
    }
    proj_kernel<<<BN/32, 64>>>(proj_w, proj_b, out, (NL - 1) & 1);
}